// round 6
// baseline (speedup 1.0000x reference)
#include <cuda_runtime.h>
#include <cstdint>

// ---------------------------------------------------------------------------
// GQA: B=4, S=2048, E=1024, H=16, G=4, HPG=4, HD=64, KV_DIM=256
// Round 6: attention occupancy fix (256 threads / 8 warps / 256 q-rows per
// CTA; warp tile unchanged 32x64). K+V projections fused into one launch.
// ---------------------------------------------------------------------------

#define B_   4
#define S_   2048
#define E_   1024
#define G_   4
#define HD_  64
#define KV_  256
#define M_   (B_ * S_)

__device__ float g_Q[(size_t)M_ * E_];
__device__ float g_K[(size_t)M_ * KV_];
__device__ float g_V[(size_t)M_ * KV_];
__device__ float g_A[(size_t)M_ * E_];

__device__ __forceinline__ unsigned f2tf(float x) {
    unsigned r;
    asm("cvt.rna.tf32.f32 %0, %1;" : "=r"(r) : "f"(x));
    return r;
}

__device__ __forceinline__ void mma_tf32(float* c, const unsigned* a, const unsigned* b) {
    asm volatile(
        "mma.sync.aligned.m16n8k8.row.col.f32.tf32.tf32.f32 "
        "{%0,%1,%2,%3}, {%4,%5,%6,%7}, {%8,%9}, {%0,%1,%2,%3};\n"
        : "+f"(c[0]), "+f"(c[1]), "+f"(c[2]), "+f"(c[3])
        : "r"(a[0]), "r"(a[1]), "r"(a[2]), "r"(a[3]),
          "r"(b[0]), "r"(b[1]));
}

// ---------------------------------------------------------------------------
// tf32 GEMM body: C[M,N] = A[M,K] @ W[K,N] + bias[N]
// 128x128 block tile at (bx, by), BK=32, 256 threads, warp tile 64x32.
// ---------------------------------------------------------------------------
#define GSTR 136

__device__ __forceinline__ void gemm_body(
    const float* __restrict__ A, const float* __restrict__ W,
    const float* __restrict__ bias, float* __restrict__ C,
    int M, int N, int K, int bx, int by)
{
    __shared__ unsigned As[32][GSTR];
    __shared__ unsigned Bs[32][GSTR];

    const int tid  = threadIdx.x;
    const int lane = tid & 31;
    const int warp = tid >> 5;
    const int gid  = lane >> 2;
    const int tg   = lane & 3;
    const int wm0  = (warp >> 2) * 64;
    const int wn0  = (warp & 3) * 32;
    const int row0 = by * 128;
    const int col0 = bx * 128;

    const int arow  = tid >> 1;
    const int acol0 = (tid & 1) * 16;
    const int bkr   = tid >> 5;
    const int bc4   = tid & 31;

    const float* Abase = A + (size_t)(row0 + arow) * K + acol0;
    const float* Wbase = W + (size_t)bkr * N + col0 + bc4 * 4;

    float4 pa[4], pb[4];

#pragma unroll
    for (int i = 0; i < 4; i++) pa[i] = *(const float4*)(Abase + i * 4);
#pragma unroll
    for (int j = 0; j < 4; j++) pb[j] = *(const float4*)(Wbase + (size_t)(8 * j) * N);

#pragma unroll
    for (int i = 0; i < 4; i++) {
        As[acol0 + i * 4 + 0][arow] = f2tf(pa[i].x);
        As[acol0 + i * 4 + 1][arow] = f2tf(pa[i].y);
        As[acol0 + i * 4 + 2][arow] = f2tf(pa[i].z);
        As[acol0 + i * 4 + 3][arow] = f2tf(pa[i].w);
    }
#pragma unroll
    for (int j = 0; j < 4; j++) {
        unsigned* dst = &Bs[bkr + 8 * j][bc4 * 4];
        dst[0] = f2tf(pb[j].x); dst[1] = f2tf(pb[j].y);
        dst[2] = f2tf(pb[j].z); dst[3] = f2tf(pb[j].w);
    }
    __syncthreads();

    float acc[4][4][4];
#pragma unroll
    for (int mt = 0; mt < 4; mt++)
#pragma unroll
        for (int nt = 0; nt < 4; nt++)
#pragma unroll
            for (int r = 0; r < 4; r++) acc[mt][nt][r] = 0.0f;

    for (int k0 = 0; k0 < K; k0 += 32) {
        const bool has_next = (k0 + 32) < K;
        if (has_next) {
#pragma unroll
            for (int i = 0; i < 4; i++)
                pa[i] = *(const float4*)(Abase + (k0 + 32) + i * 4);
#pragma unroll
            for (int j = 0; j < 4; j++)
                pb[j] = *(const float4*)(Wbase + (size_t)(k0 + 32 + 8 * j) * N);
        }

#pragma unroll
        for (int ks = 0; ks < 4; ks++) {
            unsigned a[4][4];
            unsigned b[4][2];
#pragma unroll
            for (int mt = 0; mt < 4; mt++) {
                int m = wm0 + mt * 16 + gid;
                a[mt][0] = As[ks * 8 + tg][m];
                a[mt][1] = As[ks * 8 + tg][m + 8];
                a[mt][2] = As[ks * 8 + tg + 4][m];
                a[mt][3] = As[ks * 8 + tg + 4][m + 8];
            }
#pragma unroll
            for (int nt = 0; nt < 4; nt++) {
                b[nt][0] = Bs[ks * 8 + tg][wn0 + nt * 8 + gid];
                b[nt][1] = Bs[ks * 8 + tg + 4][wn0 + nt * 8 + gid];
            }
#pragma unroll
            for (int mt = 0; mt < 4; mt++)
#pragma unroll
                for (int nt = 0; nt < 4; nt++)
                    mma_tf32(acc[mt][nt], a[mt], b[nt]);
        }
        __syncthreads();

        if (has_next) {
#pragma unroll
            for (int i = 0; i < 4; i++) {
                As[acol0 + i * 4 + 0][arow] = f2tf(pa[i].x);
                As[acol0 + i * 4 + 1][arow] = f2tf(pa[i].y);
                As[acol0 + i * 4 + 2][arow] = f2tf(pa[i].z);
                As[acol0 + i * 4 + 3][arow] = f2tf(pa[i].w);
            }
#pragma unroll
            for (int j = 0; j < 4; j++) {
                unsigned* dst = &Bs[bkr + 8 * j][bc4 * 4];
                dst[0] = f2tf(pb[j].x); dst[1] = f2tf(pb[j].y);
                dst[2] = f2tf(pb[j].z); dst[3] = f2tf(pb[j].w);
            }
            __syncthreads();
        }
    }

#pragma unroll
    for (int mt = 0; mt < 4; mt++) {
        int r0 = row0 + wm0 + mt * 16 + gid;
#pragma unroll
        for (int nt = 0; nt < 4; nt++) {
            int c = col0 + wn0 + nt * 8 + 2 * tg;
            float bx0 = bias[c], by0 = bias[c + 1];
            float2 v0 = make_float2(acc[mt][nt][0] + bx0, acc[mt][nt][1] + by0);
            float2 v1 = make_float2(acc[mt][nt][2] + bx0, acc[mt][nt][3] + by0);
            *(float2*)&C[(size_t)r0 * N + c]       = v0;
            *(float2*)&C[(size_t)(r0 + 8) * N + c] = v1;
        }
    }
}

__global__ __launch_bounds__(256) void gemm_tf32(
    const float* __restrict__ A, const float* __restrict__ W,
    const float* __restrict__ bias, float* __restrict__ C,
    int M, int N, int K)
{
    gemm_body(A, W, bias, C, M, N, K, blockIdx.x, blockIdx.y);
}

// Fused K+V projection: grid.x = 4; x<2 -> K tile col x, x>=2 -> V tile col x-2.
__global__ __launch_bounds__(256) void gemm_kv_tf32(
    const float* __restrict__ A,
    const float* __restrict__ Wk, const float* __restrict__ bk, float* __restrict__ Kp,
    const float* __restrict__ Wv, const float* __restrict__ bv, float* __restrict__ Vp)
{
    const bool is_v = (blockIdx.x >= 2);
    gemm_body(A,
              is_v ? Wv : Wk,
              is_v ? bv : bk,
              is_v ? Vp : Kp,
              M_, KV_, E_,
              is_v ? (int)blockIdx.x - 2 : (int)blockIdx.x,
              blockIdx.y);
}

// ---------------------------------------------------------------------------
// Flash attention, tf32 mma. 256 threads (8 warps). Block covers 256 q-rows;
// warp w covers rows w*32..w*32+31 (2 m-tiles of 16). 64-key tiles.
// K and V stored natural [key][d] (row.col MMA B = col-major = natural K/V).
// Grid: (S/256, B*16); blockIdx.y = b*16 + grp*4 + p.
// Output permuted: col = p*256 + grp*64 + d.
// ---------------------------------------------------------------------------
#define QROWS 256
#define NTHR  256
#define QSTR  68
#define KSTR  72

__global__ __launch_bounds__(NTHR) void attn_tf32(
    const float* __restrict__ Qg, const float* __restrict__ Kg,
    const float* __restrict__ Vg, float* __restrict__ Ag)
{
    extern __shared__ unsigned smx[];
    unsigned (*Qs)[QSTR] = (unsigned(*)[QSTR])(smx);                               // [256][68]
    unsigned (*Ks)[KSTR] = (unsigned(*)[KSTR])(smx + QROWS * QSTR);                // [key][d]
    unsigned (*Vs)[KSTR] = (unsigned(*)[KSTR])(smx + QROWS * QSTR + 64 * KSTR);    // [key][d]
    unsigned (*Ps)[QSTR] = (unsigned(*)[QSTR])(smx + QROWS * QSTR + 128 * KSTR);   // [q][key]

    const int tid  = threadIdx.x;
    const int lane = tid & 31;
    const int warp = tid >> 5;
    const int gid  = lane >> 2;
    const int tg   = lane & 3;
    const int wq0  = warp * 32;

    const int q0   = blockIdx.x * QROWS;
    const int head = blockIdx.y;
    const int b    = head >> 4;
    const int grp  = (head >> 2) & 3;
    const int p    = head & 3;
    const int h    = grp * 4 + p;

    // Load Q tile: 256 rows x 64 d, scaled by 1/8, tf32-rounded.
#pragma unroll
    for (int i = 0; i < 16; i++) {
        int idx = tid + NTHR * i;
        int r = idx >> 4;
        int d = (idx & 15) * 4;
        float4 v = *(const float4*)(Qg + (size_t)(b * S_ + q0 + r) * E_ + h * HD_ + d);
        uint4 t;
        t.x = f2tf(v.x * 0.125f); t.y = f2tf(v.y * 0.125f);
        t.z = f2tf(v.z * 0.125f); t.w = f2tf(v.w * 0.125f);
        *(uint4*)&Qs[r][d] = t;
    }

    float oacc[2][8][4];
#pragma unroll
    for (int mt = 0; mt < 2; mt++)
#pragma unroll
        for (int nt = 0; nt < 8; nt++)
#pragma unroll
            for (int r = 0; r < 4; r++) oacc[mt][nt][r] = 0.0f;

    float mrow[2][2], lrow[2][2];
#pragma unroll
    for (int mt = 0; mt < 2; mt++) {
        mrow[mt][0] = -1e30f; mrow[mt][1] = -1e30f;
        lrow[mt][0] = 0.0f;   lrow[mt][1] = 0.0f;
    }

    for (int kv0 = 0; kv0 < S_; kv0 += 64) {
        __syncthreads();   // previous tile done with Ks/Vs (Qs on iter 0)

        // Fill K and V tiles (natural [key][d]), vectorized STS.128.
#pragma unroll
        for (int i = 0; i < 4; i++) {
            int idx = tid + NTHR * i;
            int c = idx >> 4;            // key 0..63
            int d = (idx & 15) * 4;
            size_t base = (size_t)(b * S_ + kv0 + c) * KV_ + grp * HD_ + d;
            float4 kv = *(const float4*)(Kg + base);
            uint4 tk;
            tk.x = f2tf(kv.x); tk.y = f2tf(kv.y); tk.z = f2tf(kv.z); tk.w = f2tf(kv.w);
            *(uint4*)&Ks[c][d] = tk;
            float4 vv = *(const float4*)(Vg + base);
            uint4 tv;
            tv.x = f2tf(vv.x); tv.y = f2tf(vv.y); tv.z = f2tf(vv.z); tv.w = f2tf(vv.w);
            *(uint4*)&Vs[c][d] = tv;
        }
        __syncthreads();

        // ---- S = Q @ K^T : warp tile 32 x 64 ----
        float sacc[2][8][4];
#pragma unroll
        for (int mt = 0; mt < 2; mt++)
#pragma unroll
            for (int nt = 0; nt < 8; nt++)
#pragma unroll
                for (int r = 0; r < 4; r++) sacc[mt][nt][r] = 0.0f;

#pragma unroll
        for (int ks = 0; ks < 8; ks++) {
            unsigned a[2][4];
#pragma unroll
            for (int mt = 0; mt < 2; mt++) {
                int row = wq0 + mt * 16 + gid;
                a[mt][0] = Qs[row][ks * 8 + tg];
                a[mt][1] = Qs[row + 8][ks * 8 + tg];
                a[mt][2] = Qs[row][ks * 8 + tg + 4];
                a[mt][3] = Qs[row + 8][ks * 8 + tg + 4];
            }
            unsigned bb[8][2];
#pragma unroll
            for (int nt = 0; nt < 8; nt++) {
                bb[nt][0] = Ks[nt * 8 + gid][ks * 8 + tg];
                bb[nt][1] = Ks[nt * 8 + gid][ks * 8 + tg + 4];
            }
#pragma unroll
            for (int mt = 0; mt < 2; mt++)
#pragma unroll
                for (int nt = 0; nt < 8; nt++)
                    mma_tf32(sacc[mt][nt], a[mt], bb[nt]);
        }

        // ---- online softmax (per mt; lane owns rows wq0+mt*16+gid, +8) ----
#pragma unroll
        for (int mt = 0; mt < 2; mt++) {
            float rmax0 = -1e30f, rmax1 = -1e30f;
#pragma unroll
            for (int nt = 0; nt < 8; nt++) {
                rmax0 = fmaxf(rmax0, fmaxf(sacc[mt][nt][0], sacc[mt][nt][1]));
                rmax1 = fmaxf(rmax1, fmaxf(sacc[mt][nt][2], sacc[mt][nt][3]));
            }
            rmax0 = fmaxf(rmax0, __shfl_xor_sync(0xffffffffu, rmax0, 1));
            rmax0 = fmaxf(rmax0, __shfl_xor_sync(0xffffffffu, rmax0, 2));
            rmax1 = fmaxf(rmax1, __shfl_xor_sync(0xffffffffu, rmax1, 1));
            rmax1 = fmaxf(rmax1, __shfl_xor_sync(0xffffffffu, rmax1, 2));

            float nm0 = fmaxf(mrow[mt][0], rmax0);
            float nm1 = fmaxf(mrow[mt][1], rmax1);
            float corr0 = __expf(mrow[mt][0] - nm0);
            float corr1 = __expf(mrow[mt][1] - nm1);
            float sum0 = 0.0f, sum1 = 0.0f;

            int r1 = wq0 + mt * 16 + gid;
#pragma unroll
            for (int nt = 0; nt < 8; nt++) {
                float e0 = __expf(sacc[mt][nt][0] - nm0);
                float e1 = __expf(sacc[mt][nt][1] - nm0);
                float e2 = __expf(sacc[mt][nt][2] - nm1);
                float e3 = __expf(sacc[mt][nt][3] - nm1);
                sum0 += e0 + e1;
                sum1 += e2 + e3;
                uint2 p01 = make_uint2(f2tf(e0), f2tf(e1));
                uint2 p23 = make_uint2(f2tf(e2), f2tf(e3));
                *(uint2*)&Ps[r1][nt * 8 + 2 * tg]     = p01;
                *(uint2*)&Ps[r1 + 8][nt * 8 + 2 * tg] = p23;
                oacc[mt][nt][0] *= corr0; oacc[mt][nt][1] *= corr0;
                oacc[mt][nt][2] *= corr1; oacc[mt][nt][3] *= corr1;
            }
            sum0 += __shfl_xor_sync(0xffffffffu, sum0, 1);
            sum0 += __shfl_xor_sync(0xffffffffu, sum0, 2);
            sum1 += __shfl_xor_sync(0xffffffffu, sum1, 1);
            sum1 += __shfl_xor_sync(0xffffffffu, sum1, 2);
            mrow[mt][0] = nm0; mrow[mt][1] = nm1;
            lrow[mt][0] = lrow[mt][0] * corr0 + sum0;
            lrow[mt][1] = lrow[mt][1] * corr1 + sum1;
        }

        __syncwarp();   // Ps rows are warp-private

        // ---- O += P @ V : warp tile 32 x 64, k = 64 keys ----
#pragma unroll
        for (int ks = 0; ks < 8; ks++) {
            unsigned a[2][4];
#pragma unroll
            for (int mt = 0; mt < 2; mt++) {
                int row = wq0 + mt * 16 + gid;
                a[mt][0] = Ps[row][ks * 8 + tg];
                a[mt][1] = Ps[row + 8][ks * 8 + tg];
                a[mt][2] = Ps[row][ks * 8 + tg + 4];
                a[mt][3] = Ps[row + 8][ks * 8 + tg + 4];
            }
            unsigned bb[8][2];
#pragma unroll
            for (int nt = 0; nt < 8; nt++) {
                bb[nt][0] = Vs[ks * 8 + tg][nt * 8 + gid];
                bb[nt][1] = Vs[ks * 8 + tg + 4][nt * 8 + gid];
            }
#pragma unroll
            for (int mt = 0; mt < 2; mt++)
#pragma unroll
                for (int nt = 0; nt < 8; nt++)
                    mma_tf32(oacc[mt][nt], a[mt], bb[nt]);
        }
    }

    // Normalize + store permuted: col = p*256 + grp*64 + d
    const int cbase = p * (G_ * HD_) + grp * HD_;
#pragma unroll
    for (int mt = 0; mt < 2; mt++) {
        float inv0 = 1.0f / lrow[mt][0];
        float inv1 = 1.0f / lrow[mt][1];
        int r0 = b * S_ + q0 + wq0 + mt * 16 + gid;
#pragma unroll
        for (int nt = 0; nt < 8; nt++) {
            int c = cbase + nt * 8 + 2 * tg;
            float2 v0 = make_float2(oacc[mt][nt][0] * inv0, oacc[mt][nt][1] * inv0);
            float2 v1 = make_float2(oacc[mt][nt][2] * inv1, oacc[mt][nt][3] * inv1);
            *(float2*)&Ag[(size_t)r0 * E_ + c]       = v0;
            *(float2*)&Ag[(size_t)(r0 + 8) * E_ + c] = v1;
        }
    }
}

// ---------------------------------------------------------------------------
// Launch
// ---------------------------------------------------------------------------
extern "C" void kernel_launch(void* const* d_in, const int* in_sizes, int n_in,
                              void* d_out, int out_size)
{
    const float* x  = (const float*)d_in[0];
    const float* Wq = (const float*)d_in[1];
    const float* bq = (const float*)d_in[2];
    const float* Wk = (const float*)d_in[3];
    const float* bk = (const float*)d_in[4];
    const float* Wv = (const float*)d_in[5];
    const float* bv = (const float*)d_in[6];
    const float* Wo = (const float*)d_in[7];
    const float* bo = (const float*)d_in[8];
    float* out = (float*)d_out;

    float *Qp, *Kp, *Vp, *Ap;
    cudaGetSymbolAddress((void**)&Qp, g_Q);
    cudaGetSymbolAddress((void**)&Kp, g_K);
    cudaGetSymbolAddress((void**)&Vp, g_V);
    cudaGetSymbolAddress((void**)&Ap, g_A);

    const int smem_attn =
        (QROWS * QSTR + 64 * KSTR + 64 * KSTR + QROWS * QSTR) * (int)sizeof(unsigned); // 176128
    cudaFuncSetAttribute((const void*)attn_tf32,
                         cudaFuncAttributeMaxDynamicSharedMemorySize, smem_attn);

    // Q projection
    gemm_tf32<<<dim3(E_ / 128, M_ / 128), 256>>>(x, Wq, bq, Qp, M_, E_, E_);
    // K + V projections fused
    gemm_kv_tf32<<<dim3(4, M_ / 128), 256>>>(x, Wk, bk, Kp, Wv, bv, Vp);
    // Attention (permuted output)
    attn_tf32<<<dim3(S_ / QROWS, B_ * 16), NTHR, smem_attn>>>(Qp, Kp, Vp, Ap);
    // Output projection
    gemm_tf32<<<dim3(E_ / 128, M_ / 128), 256>>>(Ap, Wo, bo, out, M_, E_, E_);
}

// round 7
// speedup vs baseline: 1.1094x; 1.1094x over previous
#include <cuda_runtime.h>
#include <cstdint>

// ---------------------------------------------------------------------------
// GQA: B=4, S=2048, E=1024, H=16, G=4, HPG=4, HD=64, KV_DIM=256
// Round 7: attention back to 4-warp/128-row CTAs (2 CTAs/SM, independent
// barriers) + KSTR 72->68 (removes 2-way bank conflict on K b-fragment LDS;
// V loads stay conflict-free at 68). GEMMs unchanged; KV launch fused.
// ---------------------------------------------------------------------------

#define B_   4
#define S_   2048
#define E_   1024
#define G_   4
#define HD_  64
#define KV_  256
#define M_   (B_ * S_)

__device__ float g_Q[(size_t)M_ * E_];
__device__ float g_K[(size_t)M_ * KV_];
__device__ float g_V[(size_t)M_ * KV_];
__device__ float g_A[(size_t)M_ * E_];

__device__ __forceinline__ unsigned f2tf(float x) {
    unsigned r;
    asm("cvt.rna.tf32.f32 %0, %1;" : "=r"(r) : "f"(x));
    return r;
}

__device__ __forceinline__ void mma_tf32(float* c, const unsigned* a, const unsigned* b) {
    asm volatile(
        "mma.sync.aligned.m16n8k8.row.col.f32.tf32.tf32.f32 "
        "{%0,%1,%2,%3}, {%4,%5,%6,%7}, {%8,%9}, {%0,%1,%2,%3};\n"
        : "+f"(c[0]), "+f"(c[1]), "+f"(c[2]), "+f"(c[3])
        : "r"(a[0]), "r"(a[1]), "r"(a[2]), "r"(a[3]),
          "r"(b[0]), "r"(b[1]));
}

// ---------------------------------------------------------------------------
// tf32 GEMM body (unchanged): C[M,N] = A[M,K] @ W[K,N] + bias[N]
// ---------------------------------------------------------------------------
#define GSTR 136

__device__ __forceinline__ void gemm_body(
    const float* __restrict__ A, const float* __restrict__ W,
    const float* __restrict__ bias, float* __restrict__ C,
    int M, int N, int K, int bx, int by)
{
    __shared__ unsigned As[32][GSTR];
    __shared__ unsigned Bs[32][GSTR];

    const int tid  = threadIdx.x;
    const int lane = tid & 31;
    const int warp = tid >> 5;
    const int gid  = lane >> 2;
    const int tg   = lane & 3;
    const int wm0  = (warp >> 2) * 64;
    const int wn0  = (warp & 3) * 32;
    const int row0 = by * 128;
    const int col0 = bx * 128;

    const int arow  = tid >> 1;
    const int acol0 = (tid & 1) * 16;
    const int bkr   = tid >> 5;
    const int bc4   = tid & 31;

    const float* Abase = A + (size_t)(row0 + arow) * K + acol0;
    const float* Wbase = W + (size_t)bkr * N + col0 + bc4 * 4;

    float4 pa[4], pb[4];

#pragma unroll
    for (int i = 0; i < 4; i++) pa[i] = *(const float4*)(Abase + i * 4);
#pragma unroll
    for (int j = 0; j < 4; j++) pb[j] = *(const float4*)(Wbase + (size_t)(8 * j) * N);

#pragma unroll
    for (int i = 0; i < 4; i++) {
        As[acol0 + i * 4 + 0][arow] = f2tf(pa[i].x);
        As[acol0 + i * 4 + 1][arow] = f2tf(pa[i].y);
        As[acol0 + i * 4 + 2][arow] = f2tf(pa[i].z);
        As[acol0 + i * 4 + 3][arow] = f2tf(pa[i].w);
    }
#pragma unroll
    for (int j = 0; j < 4; j++) {
        unsigned* dst = &Bs[bkr + 8 * j][bc4 * 4];
        dst[0] = f2tf(pb[j].x); dst[1] = f2tf(pb[j].y);
        dst[2] = f2tf(pb[j].z); dst[3] = f2tf(pb[j].w);
    }
    __syncthreads();

    float acc[4][4][4];
#pragma unroll
    for (int mt = 0; mt < 4; mt++)
#pragma unroll
        for (int nt = 0; nt < 4; nt++)
#pragma unroll
            for (int r = 0; r < 4; r++) acc[mt][nt][r] = 0.0f;

    for (int k0 = 0; k0 < K; k0 += 32) {
        const bool has_next = (k0 + 32) < K;
        if (has_next) {
#pragma unroll
            for (int i = 0; i < 4; i++)
                pa[i] = *(const float4*)(Abase + (k0 + 32) + i * 4);
#pragma unroll
            for (int j = 0; j < 4; j++)
                pb[j] = *(const float4*)(Wbase + (size_t)(k0 + 32 + 8 * j) * N);
        }

#pragma unroll
        for (int ks = 0; ks < 4; ks++) {
            unsigned a[4][4];
            unsigned b[4][2];
#pragma unroll
            for (int mt = 0; mt < 4; mt++) {
                int m = wm0 + mt * 16 + gid;
                a[mt][0] = As[ks * 8 + tg][m];
                a[mt][1] = As[ks * 8 + tg][m + 8];
                a[mt][2] = As[ks * 8 + tg + 4][m];
                a[mt][3] = As[ks * 8 + tg + 4][m + 8];
            }
#pragma unroll
            for (int nt = 0; nt < 4; nt++) {
                b[nt][0] = Bs[ks * 8 + tg][wn0 + nt * 8 + gid];
                b[nt][1] = Bs[ks * 8 + tg + 4][wn0 + nt * 8 + gid];
            }
#pragma unroll
            for (int mt = 0; mt < 4; mt++)
#pragma unroll
                for (int nt = 0; nt < 4; nt++)
                    mma_tf32(acc[mt][nt], a[mt], b[nt]);
        }
        __syncthreads();

        if (has_next) {
#pragma unroll
            for (int i = 0; i < 4; i++) {
                As[acol0 + i * 4 + 0][arow] = f2tf(pa[i].x);
                As[acol0 + i * 4 + 1][arow] = f2tf(pa[i].y);
                As[acol0 + i * 4 + 2][arow] = f2tf(pa[i].z);
                As[acol0 + i * 4 + 3][arow] = f2tf(pa[i].w);
            }
#pragma unroll
            for (int j = 0; j < 4; j++) {
                unsigned* dst = &Bs[bkr + 8 * j][bc4 * 4];
                dst[0] = f2tf(pb[j].x); dst[1] = f2tf(pb[j].y);
                dst[2] = f2tf(pb[j].z); dst[3] = f2tf(pb[j].w);
            }
            __syncthreads();
        }
    }

#pragma unroll
    for (int mt = 0; mt < 4; mt++) {
        int r0 = row0 + wm0 + mt * 16 + gid;
#pragma unroll
        for (int nt = 0; nt < 4; nt++) {
            int c = col0 + wn0 + nt * 8 + 2 * tg;
            float bx0 = bias[c], by0 = bias[c + 1];
            float2 v0 = make_float2(acc[mt][nt][0] + bx0, acc[mt][nt][1] + by0);
            float2 v1 = make_float2(acc[mt][nt][2] + bx0, acc[mt][nt][3] + by0);
            *(float2*)&C[(size_t)r0 * N + c]       = v0;
            *(float2*)&C[(size_t)(r0 + 8) * N + c] = v1;
        }
    }
}

__global__ __launch_bounds__(256) void gemm_tf32(
    const float* __restrict__ A, const float* __restrict__ W,
    const float* __restrict__ bias, float* __restrict__ C,
    int M, int N, int K)
{
    gemm_body(A, W, bias, C, M, N, K, blockIdx.x, blockIdx.y);
}

__global__ __launch_bounds__(256) void gemm_kv_tf32(
    const float* __restrict__ A,
    const float* __restrict__ Wk, const float* __restrict__ bk, float* __restrict__ Kp,
    const float* __restrict__ Wv, const float* __restrict__ bv, float* __restrict__ Vp)
{
    const bool is_v = (blockIdx.x >= 2);
    gemm_body(A,
              is_v ? Wv : Wk,
              is_v ? bv : bk,
              is_v ? Vp : Kp,
              M_, KV_, E_,
              is_v ? (int)blockIdx.x - 2 : (int)blockIdx.x,
              blockIdx.y);
}

// ---------------------------------------------------------------------------
// Flash attention, tf32 mma. 128 threads (4 warps), 128 q-rows per CTA
// (warp w: rows w*32..w*32+31, 2 m-tiles of 16). 64-key tiles.
// K and V stored natural [key][d] with stride 68:
//   K b-frag load bank = (4*gid + tg)        -> 32 distinct (conflict-free)
//   V b-frag load bank = (4*tg + 8*nt + gid) -> conflict-free
// smem 104448 B -> 2 CTAs/SM (independent barrier domains overlap phases).
// Grid: (S/128, B*16); blockIdx.y = b*16 + grp*4 + p.
// Output permuted: col = p*256 + grp*64 + d.
// ---------------------------------------------------------------------------
#define QROWS 128
#define NTHR  128
#define QSTR  68
#define KSTR  68

__global__ __launch_bounds__(NTHR) void attn_tf32(
    const float* __restrict__ Qg, const float* __restrict__ Kg,
    const float* __restrict__ Vg, float* __restrict__ Ag)
{
    extern __shared__ unsigned smx[];
    unsigned (*Qs)[QSTR] = (unsigned(*)[QSTR])(smx);                               // [128][68]
    unsigned (*Ks)[KSTR] = (unsigned(*)[KSTR])(smx + QROWS * QSTR);                // [key][d]
    unsigned (*Vs)[KSTR] = (unsigned(*)[KSTR])(smx + QROWS * QSTR + 64 * KSTR);    // [key][d]
    unsigned (*Ps)[QSTR] = (unsigned(*)[QSTR])(smx + QROWS * QSTR + 128 * KSTR);   // [q][key]

    const int tid  = threadIdx.x;
    const int lane = tid & 31;
    const int warp = tid >> 5;
    const int gid  = lane >> 2;
    const int tg   = lane & 3;
    const int wq0  = warp * 32;

    const int q0   = blockIdx.x * QROWS;
    const int head = blockIdx.y;
    const int b    = head >> 4;
    const int grp  = (head >> 2) & 3;
    const int p    = head & 3;
    const int h    = grp * 4 + p;

    // Load Q tile: 128 rows x 64 d, scaled by 1/8, tf32-rounded.
#pragma unroll
    for (int i = 0; i < 16; i++) {
        int idx = tid + NTHR * i;
        int r = idx >> 4;
        int d = (idx & 15) * 4;
        float4 v = *(const float4*)(Qg + (size_t)(b * S_ + q0 + r) * E_ + h * HD_ + d);
        uint4 t;
        t.x = f2tf(v.x * 0.125f); t.y = f2tf(v.y * 0.125f);
        t.z = f2tf(v.z * 0.125f); t.w = f2tf(v.w * 0.125f);
        *(uint4*)&Qs[r][d] = t;
    }

    float oacc[2][8][4];
#pragma unroll
    for (int mt = 0; mt < 2; mt++)
#pragma unroll
        for (int nt = 0; nt < 8; nt++)
#pragma unroll
            for (int r = 0; r < 4; r++) oacc[mt][nt][r] = 0.0f;

    float mrow[2][2], lrow[2][2];
#pragma unroll
    for (int mt = 0; mt < 2; mt++) {
        mrow[mt][0] = -1e30f; mrow[mt][1] = -1e30f;
        lrow[mt][0] = 0.0f;   lrow[mt][1] = 0.0f;
    }

    for (int kv0 = 0; kv0 < S_; kv0 += 64) {
        __syncthreads();   // previous tile done with Ks/Vs (Qs on iter 0)

        // Fill K and V tiles (natural [key][d]), STS.128.
#pragma unroll
        for (int i = 0; i < 8; i++) {
            int idx = tid + NTHR * i;
            int c = idx >> 4;            // key 0..63
            int d = (idx & 15) * 4;
            size_t base = (size_t)(b * S_ + kv0 + c) * KV_ + grp * HD_ + d;
            float4 kv = *(const float4*)(Kg + base);
            uint4 tk;
            tk.x = f2tf(kv.x); tk.y = f2tf(kv.y); tk.z = f2tf(kv.z); tk.w = f2tf(kv.w);
            *(uint4*)&Ks[c][d] = tk;
            float4 vv = *(const float4*)(Vg + base);
            uint4 tv;
            tv.x = f2tf(vv.x); tv.y = f2tf(vv.y); tv.z = f2tf(vv.z); tv.w = f2tf(vv.w);
            *(uint4*)&Vs[c][d] = tv;
        }
        __syncthreads();

        // ---- S = Q @ K^T : warp tile 32 x 64 ----
        float sacc[2][8][4];
#pragma unroll
        for (int mt = 0; mt < 2; mt++)
#pragma unroll
            for (int nt = 0; nt < 8; nt++)
#pragma unroll
                for (int r = 0; r < 4; r++) sacc[mt][nt][r] = 0.0f;

#pragma unroll
        for (int ks = 0; ks < 8; ks++) {
            unsigned a[2][4];
#pragma unroll
            for (int mt = 0; mt < 2; mt++) {
                int row = wq0 + mt * 16 + gid;
                a[mt][0] = Qs[row][ks * 8 + tg];
                a[mt][1] = Qs[row + 8][ks * 8 + tg];
                a[mt][2] = Qs[row][ks * 8 + tg + 4];
                a[mt][3] = Qs[row + 8][ks * 8 + tg + 4];
            }
            unsigned bb[8][2];
#pragma unroll
            for (int nt = 0; nt < 8; nt++) {
                bb[nt][0] = Ks[nt * 8 + gid][ks * 8 + tg];
                bb[nt][1] = Ks[nt * 8 + gid][ks * 8 + tg + 4];
            }
#pragma unroll
            for (int mt = 0; mt < 2; mt++)
#pragma unroll
                for (int nt = 0; nt < 8; nt++)
                    mma_tf32(sacc[mt][nt], a[mt], bb[nt]);
        }

        // ---- online softmax ----
#pragma unroll
        for (int mt = 0; mt < 2; mt++) {
            float rmax0 = -1e30f, rmax1 = -1e30f;
#pragma unroll
            for (int nt = 0; nt < 8; nt++) {
                rmax0 = fmaxf(rmax0, fmaxf(sacc[mt][nt][0], sacc[mt][nt][1]));
                rmax1 = fmaxf(rmax1, fmaxf(sacc[mt][nt][2], sacc[mt][nt][3]));
            }
            rmax0 = fmaxf(rmax0, __shfl_xor_sync(0xffffffffu, rmax0, 1));
            rmax0 = fmaxf(rmax0, __shfl_xor_sync(0xffffffffu, rmax0, 2));
            rmax1 = fmaxf(rmax1, __shfl_xor_sync(0xffffffffu, rmax1, 1));
            rmax1 = fmaxf(rmax1, __shfl_xor_sync(0xffffffffu, rmax1, 2));

            float nm0 = fmaxf(mrow[mt][0], rmax0);
            float nm1 = fmaxf(mrow[mt][1], rmax1);
            float corr0 = __expf(mrow[mt][0] - nm0);
            float corr1 = __expf(mrow[mt][1] - nm1);
            float sum0 = 0.0f, sum1 = 0.0f;

            int r1 = wq0 + mt * 16 + gid;
#pragma unroll
            for (int nt = 0; nt < 8; nt++) {
                float e0 = __expf(sacc[mt][nt][0] - nm0);
                float e1 = __expf(sacc[mt][nt][1] - nm0);
                float e2 = __expf(sacc[mt][nt][2] - nm1);
                float e3 = __expf(sacc[mt][nt][3] - nm1);
                sum0 += e0 + e1;
                sum1 += e2 + e3;
                uint2 p01 = make_uint2(f2tf(e0), f2tf(e1));
                uint2 p23 = make_uint2(f2tf(e2), f2tf(e3));
                *(uint2*)&Ps[r1][nt * 8 + 2 * tg]     = p01;
                *(uint2*)&Ps[r1 + 8][nt * 8 + 2 * tg] = p23;
                oacc[mt][nt][0] *= corr0; oacc[mt][nt][1] *= corr0;
                oacc[mt][nt][2] *= corr1; oacc[mt][nt][3] *= corr1;
            }
            sum0 += __shfl_xor_sync(0xffffffffu, sum0, 1);
            sum0 += __shfl_xor_sync(0xffffffffu, sum0, 2);
            sum1 += __shfl_xor_sync(0xffffffffu, sum1, 1);
            sum1 += __shfl_xor_sync(0xffffffffu, sum1, 2);
            mrow[mt][0] = nm0; mrow[mt][1] = nm1;
            lrow[mt][0] = lrow[mt][0] * corr0 + sum0;
            lrow[mt][1] = lrow[mt][1] * corr1 + sum1;
        }

        __syncwarp();   // Ps rows are warp-private

        // ---- O += P @ V : warp tile 32 x 64 ----
#pragma unroll
        for (int ks = 0; ks < 8; ks++) {
            unsigned a[2][4];
#pragma unroll
            for (int mt = 0; mt < 2; mt++) {
                int row = wq0 + mt * 16 + gid;
                a[mt][0] = Ps[row][ks * 8 + tg];
                a[mt][1] = Ps[row + 8][ks * 8 + tg];
                a[mt][2] = Ps[row][ks * 8 + tg + 4];
                a[mt][3] = Ps[row + 8][ks * 8 + tg + 4];
            }
            unsigned bb[8][2];
#pragma unroll
            for (int nt = 0; nt < 8; nt++) {
                bb[nt][0] = Vs[ks * 8 + tg][nt * 8 + gid];
                bb[nt][1] = Vs[ks * 8 + tg + 4][nt * 8 + gid];
            }
#pragma unroll
            for (int mt = 0; mt < 2; mt++)
#pragma unroll
                for (int nt = 0; nt < 8; nt++)
                    mma_tf32(oacc[mt][nt], a[mt], bb[nt]);
        }
    }

    // Normalize + store permuted: col = p*256 + grp*64 + d
    const int cbase = p * (G_ * HD_) + grp * HD_;
#pragma unroll
    for (int mt = 0; mt < 2; mt++) {
        float inv0 = 1.0f / lrow[mt][0];
        float inv1 = 1.0f / lrow[mt][1];
        int r0 = b * S_ + q0 + wq0 + mt * 16 + gid;
#pragma unroll
        for (int nt = 0; nt < 8; nt++) {
            int c = cbase + nt * 8 + 2 * tg;
            float2 v0 = make_float2(oacc[mt][nt][0] * inv0, oacc[mt][nt][1] * inv0);
            float2 v1 = make_float2(oacc[mt][nt][2] * inv1, oacc[mt][nt][3] * inv1);
            *(float2*)&Ag[(size_t)r0 * E_ + c]       = v0;
            *(float2*)&Ag[(size_t)(r0 + 8) * E_ + c] = v1;
        }
    }
}

// ---------------------------------------------------------------------------
// Launch
// ---------------------------------------------------------------------------
extern "C" void kernel_launch(void* const* d_in, const int* in_sizes, int n_in,
                              void* d_out, int out_size)
{
    const float* x  = (const float*)d_in[0];
    const float* Wq = (const float*)d_in[1];
    const float* bq = (const float*)d_in[2];
    const float* Wk = (const float*)d_in[3];
    const float* bk = (const float*)d_in[4];
    const float* Wv = (const float*)d_in[5];
    const float* bv = (const float*)d_in[6];
    const float* Wo = (const float*)d_in[7];
    const float* bo = (const float*)d_in[8];
    float* out = (float*)d_out;

    float *Qp, *Kp, *Vp, *Ap;
    cudaGetSymbolAddress((void**)&Qp, g_Q);
    cudaGetSymbolAddress((void**)&Kp, g_K);
    cudaGetSymbolAddress((void**)&Vp, g_V);
    cudaGetSymbolAddress((void**)&Ap, g_A);

    const int smem_attn =
        (QROWS * QSTR + 64 * KSTR + 64 * KSTR + QROWS * QSTR) * (int)sizeof(unsigned); // 104448
    cudaFuncSetAttribute((const void*)attn_tf32,
                         cudaFuncAttributeMaxDynamicSharedMemorySize, smem_attn);

    // Q projection
    gemm_tf32<<<dim3(E_ / 128, M_ / 128), 256>>>(x, Wq, bq, Qp, M_, E_, E_);
    // K + V projections fused
    gemm_kv_tf32<<<dim3(4, M_ / 128), 256>>>(x, Wk, bk, Kp, Wv, bv, Vp);
    // Attention (permuted output)
    attn_tf32<<<dim3(S_ / QROWS, B_ * 16), NTHR, smem_attn>>>(Qp, Kp, Vp, Ap);
    // Output projection
    gemm_tf32<<<dim3(E_ / 128, M_ / 128), 256>>>(Ap, Wo, bo, out, M_, E_, E_);
}